// round 15
// baseline (speedup 1.0000x reference)
#include <cuda_runtime.h>
#include <cuda_bf16.h>
#include <math.h>
#include <stdint.h>

// Problem dims
#define B 32
#define S 256
#define EHID 768
#define DHID 128
#define EMBD 200
#define VOC 32000
#define TT 96
#define NSTEP 95
#define KFC 1096    // DHID + EHID + EMBD
#define KLSTM 968   // EMBD + EHID
#define NCH16 70    // k-chunks of 16 (padded to 1120)
#define NCH32 35    // k-chunks of 32
#define NTILES 4000 // VOC/8 n-tiles of 8
#define MT16 192    // m16-tiles: 95 steps x 2 (rows = t*32+b, 3040) padded to 3072

// Scratch (static device globals: allowed; no runtime allocation)
__device__ uint4  g_wfrag[(size_t)NCH16 * NTILES * 32];   // bf16 hi/lo B-frags, ~143MB
__device__ uint4  g_xfragAll[(size_t)NCH16 * MT16 * 64];  // A-frags [c16][mt16][part][lane], 13.8MB
__device__ float  g_enc_proj[B * S * DHID];
__device__ float  g_xcatT[KFC * B];
__device__ float  g_xhist[NSTEP * KFC * B];               // fp32 history for exact argmax
__device__ float  g_scr[B * S];
__device__ float  g_h[2][B * DHID];
__device__ float  g_c[B * DHID];

// fast activations (validated across rounds)
__device__ __forceinline__ float sigfast(float x) {
    return __fdividef(1.0f, 1.0f + __expf(-x));
}
__device__ __forceinline__ float tanhfast(float x) {
    x = fminf(fmaxf(x, -15.0f), 15.0f);
    float e = __expf(2.0f * x);
    return __fdividef(e - 1.0f, e + 1.0f);
}

// mbarrier + bulk-copy helpers (proven R10-R13)
__device__ __forceinline__ void mbar_init(uint32_t a, uint32_t cnt) {
    asm volatile("mbarrier.init.shared.b64 [%0], %1;" :: "r"(a), "r"(cnt) : "memory");
}
__device__ __forceinline__ void mbar_expect(uint32_t a, uint32_t bytes) {
    asm volatile("mbarrier.arrive.expect_tx.shared.b64 _, [%0], %1;"
                 :: "r"(a), "r"(bytes) : "memory");
}
__device__ __forceinline__ void mbar_wait(uint32_t a, uint32_t parity) {
    uint32_t done;
    asm volatile(
        "{\n\t.reg .pred p;\n\t"
        "mbarrier.try_wait.parity.acquire.cta.shared::cta.b64 p, [%1], %2;\n\t"
        "selp.b32 %0, 1, 0, p;\n\t}"
        : "=r"(done) : "r"(a), "r"(parity) : "memory");
    if (!done) {
        asm volatile(
            "{\n\t.reg .pred P1;\n\t"
            "W_%=:\n\t"
            "mbarrier.try_wait.parity.acquire.cta.shared::cta.b64 P1, [%0], %1, 0x989680;\n\t"
            "@P1 bra.uni D_%=;\n\t"
            "bra.uni W_%=;\n\t"
            "D_%=:\n\t}"
            :: "r"(a), "r"(parity) : "memory");
    }
}
__device__ __forceinline__ void bulkcp(uint32_t dst, const void* src, uint32_t bytes,
                                       uint32_t mbar) {
    asm volatile(
        "cp.async.bulk.shared::cluster.global.mbarrier::complete_tx::bytes "
        "[%0], [%1], %2, [%3];"
        :: "r"(dst), "l"(src), "r"(bytes), "r"(mbar) : "memory");
}

// bf16 pack/split
__device__ __forceinline__ uint32_t pkbf(__nv_bfloat16 a, __nv_bfloat16 b) {
    uint32_t lo = (uint32_t)__bfloat16_as_ushort(a);
    uint32_t hi = (uint32_t)__bfloat16_as_ushort(b);
    return lo | (hi << 16);
}
__device__ __forceinline__ void split2(float v, __nv_bfloat16& h, __nv_bfloat16& l) {
    h = __float2bfloat16_rn(v);
    l = __float2bfloat16_rn(v - __bfloat162float(h));
}

// warp-level bf16 tensor-core mma, m16n8k16, fp32 accumulate
__device__ __forceinline__ void mma16816(float* d, uint32_t a0, uint32_t a1,
                                         uint32_t a2, uint32_t a3,
                                         uint32_t b0, uint32_t b1) {
    asm volatile(
        "mma.sync.aligned.m16n8k16.row.col.f32.bf16.bf16.f32 "
        "{%0,%1,%2,%3}, {%4,%5,%6,%7}, {%8,%9}, {%0,%1,%2,%3};"
        : "+f"(d[0]), "+f"(d[1]), "+f"(d[2]), "+f"(d[3])
        : "r"(a0), "r"(a1), "r"(a2), "r"(a3), "r"(b0), "r"(b1));
}

// ---------------------------------------------------------------------------
__global__ void k_init(float* __restrict__ outp) {
    int i = blockIdx.x * blockDim.x + threadIdx.x;
    if (i < B * VOC) {
        int b = i / VOC, v = i % VOC;
        outp[(size_t)b * TT * VOC + v] = 0.0f;
    }
    if (i < B * DHID) { g_h[0][i] = 0.0f; g_h[1][i] = 0.0f; g_c[i] = 0.0f; }
}

// zero the dead A-frag m16 tiles (rows 3040..3071, i.e. mt16 190,191)
__global__ void k_zfrag() {
    int i = blockIdx.x * blockDim.x + threadIdx.x;   // 70*2*64 = 8960 uint4
    if (i < NCH16 * 2 * 64) {
        int c = i / 128, rem = i % 128;
        int mt = 190 + rem / 64, e = rem % 64;
        g_xfragAll[((size_t)c * MT16 + mt) * 64 + e] = make_uint4(0, 0, 0, 0);
    }
}

// ---------------------------------------------------------------------------
// Repack fc_W [VOC][KFC] into bf16 hi/lo B-fragments (fragment-ordered). Once.
// ---------------------------------------------------------------------------
__global__ void __launch_bounds__(256) k_wprep(const float* __restrict__ W) {
    __shared__ float ws[64][17];
    int c = blockIdx.y, ng = blockIdx.x;
    int k0 = c * 16, n0g = ng * 64;
    int tid = threadIdx.x;

    for (int idx = tid; idx < 64 * 16; idx += 256) {
        int r = idx >> 4, q = idx & 15;
        int kg = k0 + q;
        ws[r][q] = (kg < KFC) ? W[(size_t)(n0g + r) * KFC + kg] : 0.0f;
    }
    __syncthreads();

    int ntl = tid >> 5;
    int l = tid & 31;
    int g = l >> 2, t4 = l & 3;
    int nr = ntl * 8 + g;
    float v0 = ws[nr][2 * t4], v1 = ws[nr][2 * t4 + 1];
    float v2 = ws[nr][2 * t4 + 8], v3 = ws[nr][2 * t4 + 9];
    __nv_bfloat16 h0, l0, h1, l1, h2, l2, h3, l3;
    split2(v0, h0, l0); split2(v1, h1, l1);
    split2(v2, h2, l2); split2(v3, h3, l3);
    uint4 o;
    o.x = pkbf(h0, h1); o.y = pkbf(h2, h3);
    o.z = pkbf(l0, l1); o.w = pkbf(l2, l3);
    int nt = ng * 8 + ntl;
    g_wfrag[((size_t)c * NTILES + nt) * 32 + l] = o;
}

// ---------------------------------------------------------------------------
// enc_proj (once)
// ---------------------------------------------------------------------------
__global__ void __launch_bounds__(128) k_encproj(const float* __restrict__ enc,
                                                 const float* __restrict__ attn_W,
                                                 const float* __restrict__ attn_b) {
    __shared__ __align__(16) float es[32 * 8];
    int j = threadIdx.x;
    int row0 = blockIdx.x * 32;
    float acc[32];
    float bj = attn_b[j];
#pragma unroll
    for (int r = 0; r < 32; r++) acc[r] = bj;
    const float* Wenc = attn_W + DHID * DHID;

    for (int k0 = 0; k0 < EHID; k0 += 8) {
        __syncthreads();
        int i0 = j;
        es[i0] = enc[(size_t)(row0 + (i0 >> 3)) * EHID + k0 + (i0 & 7)];
        int i1 = j + 128;
        es[i1] = enc[(size_t)(row0 + (i1 >> 3)) * EHID + k0 + (i1 & 7)];
        __syncthreads();
        float w[8];
#pragma unroll
        for (int kk = 0; kk < 8; kk++) w[kk] = Wenc[(size_t)(k0 + kk) * DHID + j];
#pragma unroll
        for (int r = 0; r < 32; r++) {
            const float4* e4 = (const float4*)(es + r * 8);
            float4 e0 = e4[0], e1 = e4[1];
            acc[r] = fmaf(e0.x, w[0], acc[r]); acc[r] = fmaf(e0.y, w[1], acc[r]);
            acc[r] = fmaf(e0.z, w[2], acc[r]); acc[r] = fmaf(e0.w, w[3], acc[r]);
            acc[r] = fmaf(e1.x, w[4], acc[r]); acc[r] = fmaf(e1.y, w[5], acc[r]);
            acc[r] = fmaf(e1.z, w[6], acc[r]); acc[r] = fmaf(e1.w, w[7], acc[r]);
        }
    }
#pragma unroll
    for (int r = 0; r < 32; r++)
        g_enc_proj[(size_t)(row0 + r) * DHID + j] = acc[r];
}

// ---------------------------------------------------------------------------
// Per-step raw scores: grid (16, B) = 512 blocks, 128 threads.
// ---------------------------------------------------------------------------
__global__ void __launch_bounds__(128) k_score2(
    const int* __restrict__ trg, const float* __restrict__ embt,
    const float* __restrict__ attn_W, const float* __restrict__ attn_v, int t)
{
    int sb = blockIdx.x, b = blockIdx.y;
    int tid = threadIdx.x;
    __shared__ float sh_h[DHID], sh_hp[DHID], sh_v[DHID];

    sh_h[tid] = g_h[t & 1][b * DHID + tid];
    sh_v[tid] = attn_v[tid];
    __syncthreads();

    {
        float a0 = 0.f, a1 = 0.f, a2 = 0.f, a3 = 0.f;
#pragma unroll 8
        for (int k = 0; k < DHID; k += 4) {
            a0 = fmaf(sh_h[k],     attn_W[(k)     * DHID + tid], a0);
            a1 = fmaf(sh_h[k + 1], attn_W[(k + 1) * DHID + tid], a1);
            a2 = fmaf(sh_h[k + 2], attn_W[(k + 2) * DHID + tid], a2);
            a3 = fmaf(sh_h[k + 3], attn_W[(k + 3) * DHID + tid], a3);
        }
        sh_hp[tid] = (a0 + a1) + (a2 + a3);
    }
    __syncthreads();

    int w = tid >> 5, lane = tid & 31;
    const float* epb = g_enc_proj + (size_t)b * S * DHID;
    float hp0 = sh_hp[lane],      hp1 = sh_hp[lane + 32];
    float hp2 = sh_hp[lane + 64], hp3 = sh_hp[lane + 96];
    float v0 = sh_v[lane],        v1 = sh_v[lane + 32];
    float v2 = sh_v[lane + 64],   v3 = sh_v[lane + 96];
#pragma unroll
    for (int i = 0; i < 4; i++) {
        int s = sb * 16 + w * 4 + i;
        const float* ep = epb + (size_t)s * DHID;
        float acc = tanhfast(ep[lane]      + hp0) * v0
                  + tanhfast(ep[lane + 32] + hp1) * v1
                  + tanhfast(ep[lane + 64] + hp2) * v2
                  + tanhfast(ep[lane + 96] + hp3) * v3;
#pragma unroll
        for (int o = 16; o > 0; o >>= 1)
            acc += __shfl_xor_sync(0xFFFFFFFFu, acc, o);
        if (lane == 0) g_scr[b * S + s] = acc;
    }

    if (sb == 0) {
        int tok = trg[b * TT + t];
        for (int d = tid; d < EMBD; d += 128)
            g_xcatT[(DHID + EHID + d) * B + b] = embt[(size_t)tok * EMBD + d];
    }
}

// ---------------------------------------------------------------------------
// Per-step context with fused softmax: grid (6, 32), 128 threads.
// ---------------------------------------------------------------------------
__global__ void __launch_bounds__(128) k_ctx(const float* __restrict__ enc) {
    int tid = threadIdx.x;
    int d = blockIdx.x * 128 + tid;
    int b = blockIdx.y;
    __shared__ float sa[S];
    __shared__ float red[128];

    float r0 = g_scr[b * S + tid], r1 = g_scr[b * S + tid + 128];
    red[tid] = fmaxf(r0, r1);
    __syncthreads();
    for (int off = 64; off > 0; off >>= 1) {
        if (tid < off) red[tid] = fmaxf(red[tid], red[tid + off]);
        __syncthreads();
    }
    float mx = red[0];
    __syncthreads();
    float e0 = __expf(r0 - mx), e1 = __expf(r1 - mx);
    red[tid] = e0 + e1;
    __syncthreads();
    for (int off = 64; off > 0; off >>= 1) {
        if (tid < off) red[tid] += red[tid + off];
        __syncthreads();
    }
    float inv = __fdividef(1.0f, red[0]);
    sa[tid] = e0 * inv;
    sa[tid + 128] = e1 * inv;
    __syncthreads();

    const float* e = enc + (size_t)b * S * EHID + d;
    float a[8];
#pragma unroll
    for (int j = 0; j < 8; j++) a[j] = 0.0f;
#pragma unroll 4
    for (int s = 0; s < S; s += 8) {
#pragma unroll
        for (int j = 0; j < 8; j++)
            a[j] = fmaf(sa[s + j], e[(size_t)(s + j) * EHID], a[j]);
    }
    float r = ((a[0] + a[1]) + (a[2] + a[3])) + ((a[4] + a[5]) + (a[6] + a[7]));
    g_xcatT[(DHID + d) * B + b] = r;
}

// ---------------------------------------------------------------------------
// Per-step LSTM, 2-way k-split: grid = 128 blocks, 256 threads.
// ---------------------------------------------------------------------------
__global__ void __launch_bounds__(256) k_lstm(
    const float* __restrict__ W_ih, const float* __restrict__ W_hh,
    const float* __restrict__ b_ih, const float* __restrict__ b_hh, int t)
{
    int col = blockIdx.x;
    int tid = threadIdx.x;
    int half = tid >> 7;
    int gate = (tid >> 5) & 3;
    int b = tid & 31;
    int g = gate * DHID + col;

    __shared__ float sh_hold[32 * 129];
    __shared__ float sg[8][32];

    const float* hold = g_h[t & 1];
    for (int i = tid; i < B * DHID; i += 256)
        sh_hold[(i >> 7) * 129 + (i & 127)] = hold[i];
    __syncthreads();

    const float* Wg = W_ih + (size_t)g * KLSTM;
    float a0 = 0.f, a1 = 0.f, a2 = 0.f, a3 = 0.f;
    if (half == 0) {
        a0 = b_ih[g] + b_hh[g];
        const float* xe = g_xcatT + 896 * B + b;
#pragma unroll 2
        for (int k = 0; k < 200; k += 4) {
            float4 w = *(const float4*)(Wg + k);
            a0 = fmaf(w.x, xe[(k + 0) * B], a0);
            a1 = fmaf(w.y, xe[(k + 1) * B], a1);
            a2 = fmaf(w.z, xe[(k + 2) * B], a2);
            a3 = fmaf(w.w, xe[(k + 3) * B], a3);
        }
        const float* xw = g_xcatT - 72 * B + b;
#pragma unroll 2
        for (int k = 200; k < 484; k += 4) {
            float4 w = *(const float4*)(Wg + k);
            a0 = fmaf(w.x, xw[(k + 0) * B], a0);
            a1 = fmaf(w.y, xw[(k + 1) * B], a1);
            a2 = fmaf(w.z, xw[(k + 2) * B], a2);
            a3 = fmaf(w.w, xw[(k + 3) * B], a3);
        }
    } else {
        const float* xw = g_xcatT - 72 * B + b;
#pragma unroll 2
        for (int k = 484; k < 968; k += 4) {
            float4 w = *(const float4*)(Wg + k);
            a0 = fmaf(w.x, xw[(k + 0) * B], a0);
            a1 = fmaf(w.y, xw[(k + 1) * B], a1);
            a2 = fmaf(w.z, xw[(k + 2) * B], a2);
            a3 = fmaf(w.w, xw[(k + 3) * B], a3);
        }
        const float* Wh = W_hh + (size_t)g * DHID;
        const float* hb = sh_hold + b * 129;
#pragma unroll 4
        for (int k = 0; k < DHID; k += 4) {
            float4 w = *(const float4*)(Wh + k);
            a0 = fmaf(w.x, hb[k + 0], a0);
            a1 = fmaf(w.y, hb[k + 1], a1);
            a2 = fmaf(w.z, hb[k + 2], a2);
            a3 = fmaf(w.w, hb[k + 3], a3);
        }
    }
    sg[half * 4 + gate][b] = (a0 + a1) + (a2 + a3);
    __syncthreads();

    if (tid < 32) {
        float gi = sg[0][b] + sg[4][b];
        float gf = sg[1][b] + sg[5][b];
        float gg = sg[2][b] + sg[6][b];
        float go = sg[3][b] + sg[7][b];
        float c = g_c[b * DHID + col];
        c = sigfast(gf) * c + sigfast(gi) * tanhfast(gg);
        float h = sigfast(go) * tanhfast(c);
        g_c[b * DHID + col] = c;
        g_h[(t + 1) & 1][b * DHID + col] = h;
        g_xcatT[col * B + b] = h;
    }
}

// ---------------------------------------------------------------------------
// Per-step x prep: bf16 hi/lo A-fragments into the GLOBAL step-indexed array
// (m16 tiles 2t, 2t+1) + fp32 history save. grid = NCH16, 128 threads.
// ---------------------------------------------------------------------------
__global__ void __launch_bounds__(128) k_xprep(int t) {
    __shared__ float xs[16][33];
    int c = blockIdx.x, tid = threadIdx.x;
    int k0 = c * 16;

    for (int idx = tid; idx < 512; idx += 128) {
        int kl = idx >> 5, bb = idx & 31;
        int kg = k0 + kl;
        xs[kl][bb] = (kg < KFC) ? g_xcatT[kg * B + bb] : 0.0f;
    }
    __syncthreads();

    int mt = tid >> 6;
    int l = (tid >> 1) & 31;
    int part = tid & 1;
    int g = l >> 2, t4 = l & 3;
    int b0 = mt * 16 + g;

    float v00 = xs[2 * t4][b0],     v01 = xs[2 * t4 + 1][b0];
    float v10 = xs[2 * t4][b0 + 8], v11 = xs[2 * t4 + 1][b0 + 8];
    float v20 = xs[2 * t4 + 8][b0],     v21 = xs[2 * t4 + 9][b0];
    float v30 = xs[2 * t4 + 8][b0 + 8], v31 = xs[2 * t4 + 9][b0 + 8];

    __nv_bfloat16 h00, l00, h01, l01, h10, l10, h11, l11;
    __nv_bfloat16 h20, l20, h21, l21, h30, l30, h31, l31;
    split2(v00, h00, l00); split2(v01, h01, l01);
    split2(v10, h10, l10); split2(v11, h11, l11);
    split2(v20, h20, l20); split2(v21, h21, l21);
    split2(v30, h30, l30); split2(v31, h31, l31);
    uint4 o;
    if (part == 0) {
        o.x = pkbf(h00, h01); o.y = pkbf(h10, h11);
        o.z = pkbf(h20, h21); o.w = pkbf(h30, h31);
    } else {
        o.x = pkbf(l00, l01); o.y = pkbf(l10, l11);
        o.z = pkbf(l20, l21); o.w = pkbf(l30, l31);
    }
    int mt16 = 2 * t + mt;
    g_xfragAll[(((size_t)c * MT16 + mt16) * 2 + part) * 32 + l] = o;

    for (int idx = tid; idx < 512; idx += 128) {
        int kg = k0 + (idx >> 5);
        int bb = idx & 31;
        if (kg < KFC)
            g_xhist[(size_t)t * (KFC * B) + kg * B + bb] = g_xcatT[kg * B + bb];
    }
}

// ---------------------------------------------------------------------------
// Batched FC GEMM: D[128m x 128n] per block, 3-term bf16 split, K=32-staged
// bulkcp pipeline (32KB stages: 16KB w + 16KB x). grid (250, 6 m-tiles).
// Runs on a side stream, overlapping the recurrence of later step groups.
// ---------------------------------------------------------------------------
#define GM_SMEM (3 * 32768)

#define GISSUE(c) do {                                                          \
    int s2 = (c) % 3;                                                           \
    uint32_t sd = sb + s2 * 32768u;                                             \
    mbar_expect(mb + 8 * s2, 32768u);                                           \
    bulkcp(sd,           g_wfrag + ((size_t)(2 * (c))     * NTILES + nt0) * 32, \
           8192u, mb + 8 * s2);                                                 \
    bulkcp(sd + 8192u,   g_wfrag + ((size_t)(2 * (c) + 1) * NTILES + nt0) * 32, \
           8192u, mb + 8 * s2);                                                 \
    bulkcp(sd + 16384u,  g_xfragAll + ((size_t)(2 * (c))     * MT16 + m16b) * 64,\
           8192u, mb + 8 * s2);                                                 \
    bulkcp(sd + 24576u,  g_xfragAll + ((size_t)(2 * (c) + 1) * MT16 + m16b) * 64,\
           8192u, mb + 8 * s2);                                                 \
} while (0)

__global__ void __launch_bounds__(256) k_gemm(const float* __restrict__ fc_b,
                                              float* __restrict__ outp, int mt0) {
    extern __shared__ __align__(16) uint4 swq[];          // 3 x 32KB
    __shared__ __align__(8) unsigned long long mbar_st[3];
    int tid = threadIdx.x;
    int lane = tid & 31, wrp = tid >> 5;
    int mwarp = wrp >> 1, nwarp = wrp & 1;
    int nt0 = blockIdx.x * 16;                            // 16 ntiles (128 n)
    int mtile = mt0 + blockIdx.y;                         // 128-row tile
    int m16b = mtile * 8;

    uint32_t sb = (uint32_t)__cvta_generic_to_shared(&swq[0]);
    uint32_t mb = (uint32_t)__cvta_generic_to_shared(&mbar_st[0]);

    if (tid == 0) {
#pragma unroll
        for (int s = 0; s < 3; s++) mbar_init(mb + 8 * s, 1);
    }
    __syncthreads();
    if (tid == 0) { GISSUE(0); GISSUE(1); }

    float acc[2][8][4];                                   // [m16][ntile][frag]
#pragma unroll
    for (int m = 0; m < 2; m++)
#pragma unroll
        for (int i = 0; i < 8; i++)
#pragma unroll
            for (int j = 0; j < 4; j++) acc[m][i][j] = 0.0f;

    for (int c = 0; c < NCH32; c++) {
        int slot = c % 3;
        mbar_wait(mb + 8 * slot, (uint32_t)((c / 3) & 1));
        if (tid == 0 && c + 2 < NCH32) GISSUE(c + 2);     // slot (c+2)%3 free since iter c-1

        const uint4* stg = swq + slot * 2048;
#pragma unroll
        for (int ksub = 0; ksub < 2; ksub++) {
            const uint4* xs = stg + 1024 + ksub * 512;    // [mt16(8)][part(2)][32]
            uint4 ah0 = xs[((mwarp * 2 + 0) * 2 + 0) * 32 + lane];
            uint4 al0 = xs[((mwarp * 2 + 0) * 2 + 1) * 32 + lane];
            uint4 ah1 = xs[((mwarp * 2 + 1) * 2 + 0) * 32 + lane];
            uint4 al1 = xs[((mwarp * 2 + 1) * 2 + 1) * 32 + lane];
            const uint4* ws = stg + ksub * 512 + nwarp * 8 * 32;
#pragma unroll
            for (int i = 0; i < 8; i++) {
                uint4 bq = ws[i * 32 + lane];             // {b0h,b1h,b0l,b1l}
                mma16816(acc[0][i], ah0.x, ah0.y, ah0.z, ah0.w, bq.x, bq.y);
                mma16816(acc[1][i], ah1.x, ah1.y, ah1.z, ah1.w, bq.x, bq.y);
                mma16816(acc[0][i], al0.x, al0.y, al0.z, al0.w, bq.x, bq.y);
                mma16816(acc[1][i], al1.x, al1.y, al1.z, al1.w, bq.x, bq.y);
                mma16816(acc[0][i], ah0.x, ah0.y, ah0.z, ah0.w, bq.z, bq.w);
                mma16816(acc[1][i], ah1.x, ah1.y, ah1.z, ah1.w, bq.z, bq.w);
            }
        }
        __syncthreads();                                  // slot consumed
    }

    // epilogue: c0:D[g][2t4] c1:D[g][2t4+1] c2:D[g+8][2t4] c3:D[g+8][2t4+1]
    int g = lane >> 2, t4 = lane & 3;
#pragma unroll
    for (int mi = 0; mi < 2; mi++) {
        int m16 = m16b + mwarp * 2 + mi;
        int r0 = m16 * 16 + g;                            // global rows (t*32+b)
#pragma unroll
        for (int i = 0; i < 8; i++) {
            int n = nt0 * 8 + (nwarp * 8 + i) * 8 + 2 * t4;
            float b0 = fc_b[n], b1 = fc_b[n + 1];
            int rA = r0, rB = r0 + 8;
            int tA = rA >> 5, bA = rA & 31;
            int tB = rB >> 5, bB = rB & 31;
            if (tA < NSTEP) {
                float2 o = make_float2(acc[mi][i][0] + b0, acc[mi][i][1] + b1);
                *(float2*)(outp + ((size_t)bA * TT + tA + 1) * VOC + n) = o;
            }
            if (tB < NSTEP) {
                float2 o = make_float2(acc[mi][i][2] + b0, acc[mi][i][3] + b1);
                *(float2*)(outp + ((size_t)bB * TT + tB + 1) * VOC + n) = o;
            }
        }
    }
}

// ---------------------------------------------------------------------------
// Epilogue argmax: approx top-2 scan + exact fp32 recompute of candidates.
// ---------------------------------------------------------------------------
__global__ void __launch_bounds__(256) k_argmax(const float* __restrict__ outp,
                                                const float* __restrict__ fc_W,
                                                const float* __restrict__ fc_b,
                                                float* __restrict__ tokout) {
    int row = blockIdx.x;
    int b = row / TT, tt = row % TT;
    int tid = threadIdx.x;
    if (tt == 0) { if (tid == 0) tokout[row] = 0.0f; return; }

    const float* p = outp + ((size_t)b * TT + tt) * VOC;
    __shared__ float sv[256];
    __shared__ int si[256];
    __shared__ float dre[2];

    float best = -1e30f; int bi = 0;
    for (int i = tid; i < VOC; i += 256) {
        float v = p[i];
        if (v > best) { best = v; bi = i; }
    }
    sv[tid] = best; si[tid] = bi;
    __syncthreads();
    for (int off = 128; off > 0; off >>= 1) {
        if (tid < off) {
            if (sv[tid + off] > sv[tid] ||
                (sv[tid + off] == sv[tid] && si[tid + off] < si[tid])) {
                sv[tid] = sv[tid + off]; si[tid] = si[tid + off];
            }
        }
        __syncthreads();
    }
    int i1 = si[0];
    __syncthreads();

    best = -1e30f; bi = 0;
    for (int i = tid; i < VOC; i += 256) {
        if (i == i1) continue;
        float v = p[i];
        if (v > best) { best = v; bi = i; }
    }
    sv[tid] = best; si[tid] = bi;
    __syncthreads();
    for (int off = 128; off > 0; off >>= 1) {
        if (tid < off) {
            if (sv[tid + off] > sv[tid] ||
                (sv[tid + off] == sv[tid] && si[tid + off] < si[tid])) {
                sv[tid] = sv[tid + off]; si[tid] = si[tid + off];
            }
        }
        __syncthreads();
    }
    int i2 = si[0];
    __syncthreads();

    int wrp = tid >> 5, lane = tid & 31;
    if (wrp < 2) {
        int idx = (wrp == 0) ? i1 : i2;
        const float* wr = fc_W + (size_t)idx * KFC;
        const float* xr = g_xhist + (size_t)(tt - 1) * (KFC * B);
        float a = 0.0f;
        for (int k = lane; k < KFC; k += 32)
            a = fmaf(xr[k * B + b], wr[k], a);
#pragma unroll
        for (int o = 16; o > 0; o >>= 1)
            a += __shfl_xor_sync(0xFFFFFFFFu, a, o);
        if (lane == 0) dre[wrp] = a + fc_b[idx];
    }
    __syncthreads();
    if (tid == 0) {
        float d1 = dre[0], d2 = dre[1];
        int winner = i1;
        if (d2 > d1 || (d2 == d1 && i2 < i1)) winner = i2;
        tokout[row] = (float)winner;
    }
}

// ---------------------------------------------------------------------------
extern "C" void kernel_launch(void* const* d_in, const int* in_sizes, int n_in,
                              void* d_out, int out_size) {
    const float* enc    = (const float*)d_in[0];
    const int*   trg    = (const int*)d_in[1];
    const float* embt   = (const float*)d_in[2];
    const float* attn_W = (const float*)d_in[3];
    const float* attn_b = (const float*)d_in[4];
    const float* attn_v = (const float*)d_in[5];
    const float* W_ih   = (const float*)d_in[6];
    const float* W_hh   = (const float*)d_in[7];
    const float* b_ih   = (const float*)d_in[8];
    const float* b_hh   = (const float*)d_in[9];
    const float* fc_W   = (const float*)d_in[10];
    const float* fc_b   = (const float*)d_in[11];
    float* outp = (float*)d_out;
    (void)in_sizes; (void)n_in;

    cudaFuncSetAttribute(k_gemm, cudaFuncAttributeMaxDynamicSharedMemorySize, GM_SMEM);

    // side stream + events (non-blocking: no implicit legacy-stream syncs).
    cudaStream_t sB;
    cudaStreamCreateWithFlags(&sB, cudaStreamNonBlocking);
    cudaEvent_t evg[4], evB;
    for (int i = 0; i < 4; i++) cudaEventCreateWithFlags(&evg[i], cudaEventDisableTiming);
    cudaEventCreateWithFlags(&evB, cudaEventDisableTiming);

    k_init<<<(B * VOC + 255) / 256, 256>>>(outp);
    k_zfrag<<<(NCH16 * 2 * 64 + 255) / 256, 256>>>();
    k_wprep<<<dim3(NTILES / 8, NCH16), 256>>>(fc_W);
    k_encproj<<<(B * S) / 32, 128>>>(enc, attn_W, attn_b);

    for (int t = 0; t < NSTEP; t++) {
        k_score2<<<dim3(16, B), 128>>>(trg, embt, attn_W, attn_v, t);
        k_ctx<<<dim3(EHID / 128, B), 128>>>(enc);
        k_lstm<<<DHID, 256>>>(W_ih, W_hh, b_ih, b_hh, t);
        k_xprep<<<NCH16, 128>>>(t);

        // after each group of 24 steps completes its xprep, kick its GEMM
        // chunk on the side stream. g = t/24: t=23->0, 47->1, 71->2, 94->3.
        if (t == 23 || t == 47 || t == 71 || t == 94) {
            int g = t / 24;
            cudaEventRecord(evg[g], 0);
            cudaStreamWaitEvent(sB, evg[g], 0);
            k_gemm<<<dim3(250, 6), 256, GM_SMEM, sB>>>(fc_b, outp, g * 6);
        }
    }

    // join: main stream waits for the last GEMM chunk, then argmax
    cudaEventRecord(evB, sB);
    cudaStreamWaitEvent(0, evB, 0);

    long long need = (long long)B * TT * VOC + (long long)B * TT;
    if ((long long)out_size >= need) {
        k_argmax<<<B * TT, 256>>>(outp, fc_W, fc_b,
                                  outp + (size_t)B * TT * VOC);
    }
}

// round 16
// speedup vs baseline: 1.0158x; 1.0158x over previous
#include <cuda_runtime.h>
#include <cuda_bf16.h>
#include <math.h>
#include <stdint.h>

// Problem dims
#define B 32
#define S 256
#define EHID 768
#define DHID 128
#define EMBD 200
#define VOC 32000
#define TT 96
#define NSTEP 95
#define KFC 1096    // DHID + EHID + EMBD
#define KLSTM 968   // EMBD + EHID
#define NCH16 70    // k-chunks of 16 (padded)
#define NCH32 35    // k-chunks of 32
#define NTILES 4000 // VOC/8 n-tiles of 8

// Scratch (static device globals: allowed; no runtime allocation)
__device__ uint4  g_wfrag[(size_t)NCH16 * NTILES * 32]; // bf16 hi/lo B-frags, ~143MB
__device__ uint4  g_xfragA[2][NCH16 * 2 * 2 * 32];      // ping-pong: fc(t) reads [t&1]
__device__ float  g_enc_proj[B * S * DHID];
__device__ float  g_xcatT[KFC * B];
__device__ float  g_xhist[NSTEP * KFC * B];             // fp32 history for exact argmax
__device__ float  g_scr[B * S];
__device__ float  g_h[2][B * DHID];
__device__ float  g_c[B * DHID];

// fast activations (validated across rounds)
__device__ __forceinline__ float sigfast(float x) {
    return __fdividef(1.0f, 1.0f + __expf(-x));
}
__device__ __forceinline__ float tanhfast(float x) {
    x = fminf(fmaxf(x, -15.0f), 15.0f);
    float e = __expf(2.0f * x);
    return __fdividef(e - 1.0f, e + 1.0f);
}

// mbarrier + bulk-copy helpers (proven R10-R13)
__device__ __forceinline__ void mbar_init(uint32_t a, uint32_t cnt) {
    asm volatile("mbarrier.init.shared.b64 [%0], %1;" :: "r"(a), "r"(cnt) : "memory");
}
__device__ __forceinline__ void mbar_expect(uint32_t a, uint32_t bytes) {
    asm volatile("mbarrier.arrive.expect_tx.shared.b64 _, [%0], %1;"
                 :: "r"(a), "r"(bytes) : "memory");
}
__device__ __forceinline__ void mbar_wait(uint32_t a, uint32_t parity) {
    uint32_t done;
    asm volatile(
        "{\n\t.reg .pred p;\n\t"
        "mbarrier.try_wait.parity.acquire.cta.shared::cta.b64 p, [%1], %2;\n\t"
        "selp.b32 %0, 1, 0, p;\n\t}"
        : "=r"(done) : "r"(a), "r"(parity) : "memory");
    if (!done) {
        asm volatile(
            "{\n\t.reg .pred P1;\n\t"
            "W_%=:\n\t"
            "mbarrier.try_wait.parity.acquire.cta.shared::cta.b64 P1, [%0], %1, 0x989680;\n\t"
            "@P1 bra.uni D_%=;\n\t"
            "bra.uni W_%=;\n\t"
            "D_%=:\n\t}"
            :: "r"(a), "r"(parity) : "memory");
    }
}
__device__ __forceinline__ void bulkcp(uint32_t dst, const void* src, uint32_t bytes,
                                       uint32_t mbar) {
    asm volatile(
        "cp.async.bulk.shared::cluster.global.mbarrier::complete_tx::bytes "
        "[%0], [%1], %2, [%3];"
        :: "r"(dst), "l"(src), "r"(bytes), "r"(mbar) : "memory");
}

// bf16 pack/split
__device__ __forceinline__ uint32_t pkbf(__nv_bfloat16 a, __nv_bfloat16 b) {
    uint32_t lo = (uint32_t)__bfloat16_as_ushort(a);
    uint32_t hi = (uint32_t)__bfloat16_as_ushort(b);
    return lo | (hi << 16);
}
__device__ __forceinline__ void split2(float v, __nv_bfloat16& h, __nv_bfloat16& l) {
    h = __float2bfloat16_rn(v);
    l = __float2bfloat16_rn(v - __bfloat162float(h));
}

// warp-level bf16 tensor-core mma, m16n8k16, fp32 accumulate
__device__ __forceinline__ void mma16816(float* d, uint32_t a0, uint32_t a1,
                                         uint32_t a2, uint32_t a3,
                                         uint32_t b0, uint32_t b1) {
    asm volatile(
        "mma.sync.aligned.m16n8k16.row.col.f32.bf16.bf16.f32 "
        "{%0,%1,%2,%3}, {%4,%5,%6,%7}, {%8,%9}, {%0,%1,%2,%3};"
        : "+f"(d[0]), "+f"(d[1]), "+f"(d[2]), "+f"(d[3])
        : "r"(a0), "r"(a1), "r"(a2), "r"(a3), "r"(b0), "r"(b1));
}

// ---------------------------------------------------------------------------
__global__ void k_init(float* __restrict__ outp) {
    int i = blockIdx.x * blockDim.x + threadIdx.x;
    if (i < B * VOC) {
        int b = i / VOC, v = i % VOC;
        outp[(size_t)b * TT * VOC + v] = 0.0f;
    }
    if (i < B * DHID) { g_h[0][i] = 0.0f; g_h[1][i] = 0.0f; g_c[i] = 0.0f; }
}

// ---------------------------------------------------------------------------
// Repack fc_W [VOC][KFC] into bf16 hi/lo B-fragments (fragment-ordered). Once.
// ---------------------------------------------------------------------------
__global__ void __launch_bounds__(256) k_wprep(const float* __restrict__ W) {
    __shared__ float ws[64][17];
    int c = blockIdx.y, ng = blockIdx.x;
    int k0 = c * 16, n0g = ng * 64;
    int tid = threadIdx.x;

    for (int idx = tid; idx < 64 * 16; idx += 256) {
        int r = idx >> 4, q = idx & 15;
        int kg = k0 + q;
        ws[r][q] = (kg < KFC) ? W[(size_t)(n0g + r) * KFC + kg] : 0.0f;
    }
    __syncthreads();

    int ntl = tid >> 5;
    int l = tid & 31;
    int g = l >> 2, t4 = l & 3;
    int nr = ntl * 8 + g;
    float v0 = ws[nr][2 * t4], v1 = ws[nr][2 * t4 + 1];
    float v2 = ws[nr][2 * t4 + 8], v3 = ws[nr][2 * t4 + 9];
    __nv_bfloat16 h0, l0, h1, l1, h2, l2, h3, l3;
    split2(v0, h0, l0); split2(v1, h1, l1);
    split2(v2, h2, l2); split2(v3, h3, l3);
    uint4 o;
    o.x = pkbf(h0, h1); o.y = pkbf(h2, h3);
    o.z = pkbf(l0, l1); o.w = pkbf(l2, l3);
    int nt = ng * 8 + ntl;
    g_wfrag[((size_t)c * NTILES + nt) * 32 + l] = o;
}

// ---------------------------------------------------------------------------
// enc_proj (once)
// ---------------------------------------------------------------------------
__global__ void __launch_bounds__(128) k_encproj(const float* __restrict__ enc,
                                                 const float* __restrict__ attn_W,
                                                 const float* __restrict__ attn_b) {
    __shared__ __align__(16) float es[32 * 8];
    int j = threadIdx.x;
    int row0 = blockIdx.x * 32;
    float acc[32];
    float bj = attn_b[j];
#pragma unroll
    for (int r = 0; r < 32; r++) acc[r] = bj;
    const float* Wenc = attn_W + DHID * DHID;

    for (int k0 = 0; k0 < EHID; k0 += 8) {
        __syncthreads();
        int i0 = j;
        es[i0] = enc[(size_t)(row0 + (i0 >> 3)) * EHID + k0 + (i0 & 7)];
        int i1 = j + 128;
        es[i1] = enc[(size_t)(row0 + (i1 >> 3)) * EHID + k0 + (i1 & 7)];
        __syncthreads();
        float w[8];
#pragma unroll
        for (int kk = 0; kk < 8; kk++) w[kk] = Wenc[(size_t)(k0 + kk) * DHID + j];
#pragma unroll
        for (int r = 0; r < 32; r++) {
            const float4* e4 = (const float4*)(es + r * 8);
            float4 e0 = e4[0], e1 = e4[1];
            acc[r] = fmaf(e0.x, w[0], acc[r]); acc[r] = fmaf(e0.y, w[1], acc[r]);
            acc[r] = fmaf(e0.z, w[2], acc[r]); acc[r] = fmaf(e0.w, w[3], acc[r]);
            acc[r] = fmaf(e1.x, w[4], acc[r]); acc[r] = fmaf(e1.y, w[5], acc[r]);
            acc[r] = fmaf(e1.z, w[6], acc[r]); acc[r] = fmaf(e1.w, w[7], acc[r]);
        }
    }
#pragma unroll
    for (int r = 0; r < 32; r++)
        g_enc_proj[(size_t)(row0 + r) * DHID + j] = acc[r];
}

// ---------------------------------------------------------------------------
// Per-step raw scores: grid (16, B) = 512 blocks, 128 threads.
// ---------------------------------------------------------------------------
__global__ void __launch_bounds__(128) k_score2(
    const int* __restrict__ trg, const float* __restrict__ embt,
    const float* __restrict__ attn_W, const float* __restrict__ attn_v, int t)
{
    int sb = blockIdx.x, b = blockIdx.y;
    int tid = threadIdx.x;
    __shared__ float sh_h[DHID], sh_hp[DHID], sh_v[DHID];

    sh_h[tid] = g_h[t & 1][b * DHID + tid];
    sh_v[tid] = attn_v[tid];
    __syncthreads();

    {
        float a0 = 0.f, a1 = 0.f, a2 = 0.f, a3 = 0.f;
#pragma unroll 8
        for (int k = 0; k < DHID; k += 4) {
            a0 = fmaf(sh_h[k],     attn_W[(k)     * DHID + tid], a0);
            a1 = fmaf(sh_h[k + 1], attn_W[(k + 1) * DHID + tid], a1);
            a2 = fmaf(sh_h[k + 2], attn_W[(k + 2) * DHID + tid], a2);
            a3 = fmaf(sh_h[k + 3], attn_W[(k + 3) * DHID + tid], a3);
        }
        sh_hp[tid] = (a0 + a1) + (a2 + a3);
    }
    __syncthreads();

    int w = tid >> 5, lane = tid & 31;
    const float* epb = g_enc_proj + (size_t)b * S * DHID;
    float hp0 = sh_hp[lane],      hp1 = sh_hp[lane + 32];
    float hp2 = sh_hp[lane + 64], hp3 = sh_hp[lane + 96];
    float v0 = sh_v[lane],        v1 = sh_v[lane + 32];
    float v2 = sh_v[lane + 64],   v3 = sh_v[lane + 96];
#pragma unroll
    for (int i = 0; i < 4; i++) {
        int s = sb * 16 + w * 4 + i;
        const float* ep = epb + (size_t)s * DHID;
        float acc = tanhfast(ep[lane]      + hp0) * v0
                  + tanhfast(ep[lane + 32] + hp1) * v1
                  + tanhfast(ep[lane + 64] + hp2) * v2
                  + tanhfast(ep[lane + 96] + hp3) * v3;
#pragma unroll
        for (int o = 16; o > 0; o >>= 1)
            acc += __shfl_xor_sync(0xFFFFFFFFu, acc, o);
        if (lane == 0) g_scr[b * S + s] = acc;
    }

    if (sb == 0) {
        int tok = trg[b * TT + t];
        for (int d = tid; d < EMBD; d += 128)
            g_xcatT[(DHID + EHID + d) * B + b] = embt[(size_t)tok * EMBD + d];
    }
}

// ---------------------------------------------------------------------------
// Per-step context with fused softmax: grid (6, 32), 128 threads.
// ---------------------------------------------------------------------------
__global__ void __launch_bounds__(128) k_ctx(const float* __restrict__ enc) {
    int tid = threadIdx.x;
    int d = blockIdx.x * 128 + tid;
    int b = blockIdx.y;
    __shared__ float sa[S];
    __shared__ float red[128];

    float r0 = g_scr[b * S + tid], r1 = g_scr[b * S + tid + 128];
    red[tid] = fmaxf(r0, r1);
    __syncthreads();
    for (int off = 64; off > 0; off >>= 1) {
        if (tid < off) red[tid] = fmaxf(red[tid], red[tid + off]);
        __syncthreads();
    }
    float mx = red[0];
    __syncthreads();
    float e0 = __expf(r0 - mx), e1 = __expf(r1 - mx);
    red[tid] = e0 + e1;
    __syncthreads();
    for (int off = 64; off > 0; off >>= 1) {
        if (tid < off) red[tid] += red[tid + off];
        __syncthreads();
    }
    float inv = __fdividef(1.0f, red[0]);
    sa[tid] = e0 * inv;
    sa[tid + 128] = e1 * inv;
    __syncthreads();

    const float* e = enc + (size_t)b * S * EHID + d;
    float a[8];
#pragma unroll
    for (int j = 0; j < 8; j++) a[j] = 0.0f;
#pragma unroll 4
    for (int s = 0; s < S; s += 8) {
#pragma unroll
        for (int j = 0; j < 8; j++)
            a[j] = fmaf(sa[s + j], e[(size_t)(s + j) * EHID], a[j]);
    }
    float r = ((a[0] + a[1]) + (a[2] + a[3])) + ((a[4] + a[5]) + (a[6] + a[7]));
    g_xcatT[(DHID + d) * B + b] = r;
}

// ---------------------------------------------------------------------------
// Per-step LSTM, 2-way k-split: grid = 128 blocks, 256 threads.
// ---------------------------------------------------------------------------
__global__ void __launch_bounds__(256) k_lstm(
    const float* __restrict__ W_ih, const float* __restrict__ W_hh,
    const float* __restrict__ b_ih, const float* __restrict__ b_hh, int t)
{
    int col = blockIdx.x;
    int tid = threadIdx.x;
    int half = tid >> 7;
    int gate = (tid >> 5) & 3;
    int b = tid & 31;
    int g = gate * DHID + col;

    __shared__ float sh_hold[32 * 129];
    __shared__ float sg[8][32];

    const float* hold = g_h[t & 1];
    for (int i = tid; i < B * DHID; i += 256)
        sh_hold[(i >> 7) * 129 + (i & 127)] = hold[i];
    __syncthreads();

    const float* Wg = W_ih + (size_t)g * KLSTM;
    float a0 = 0.f, a1 = 0.f, a2 = 0.f, a3 = 0.f;
    if (half == 0) {
        a0 = b_ih[g] + b_hh[g];
        const float* xe = g_xcatT + 896 * B + b;
#pragma unroll 2
        for (int k = 0; k < 200; k += 4) {
            float4 w = *(const float4*)(Wg + k);
            a0 = fmaf(w.x, xe[(k + 0) * B], a0);
            a1 = fmaf(w.y, xe[(k + 1) * B], a1);
            a2 = fmaf(w.z, xe[(k + 2) * B], a2);
            a3 = fmaf(w.w, xe[(k + 3) * B], a3);
        }
        const float* xw = g_xcatT - 72 * B + b;
#pragma unroll 2
        for (int k = 200; k < 484; k += 4) {
            float4 w = *(const float4*)(Wg + k);
            a0 = fmaf(w.x, xw[(k + 0) * B], a0);
            a1 = fmaf(w.y, xw[(k + 1) * B], a1);
            a2 = fmaf(w.z, xw[(k + 2) * B], a2);
            a3 = fmaf(w.w, xw[(k + 3) * B], a3);
        }
    } else {
        const float* xw = g_xcatT - 72 * B + b;
#pragma unroll 2
        for (int k = 484; k < 968; k += 4) {
            float4 w = *(const float4*)(Wg + k);
            a0 = fmaf(w.x, xw[(k + 0) * B], a0);
            a1 = fmaf(w.y, xw[(k + 1) * B], a1);
            a2 = fmaf(w.z, xw[(k + 2) * B], a2);
            a3 = fmaf(w.w, xw[(k + 3) * B], a3);
        }
        const float* Wh = W_hh + (size_t)g * DHID;
        const float* hb = sh_hold + b * 129;
#pragma unroll 4
        for (int k = 0; k < DHID; k += 4) {
            float4 w = *(const float4*)(Wh + k);
            a0 = fmaf(w.x, hb[k + 0], a0);
            a1 = fmaf(w.y, hb[k + 1], a1);
            a2 = fmaf(w.z, hb[k + 2], a2);
            a3 = fmaf(w.w, hb[k + 3], a3);
        }
    }
    sg[half * 4 + gate][b] = (a0 + a1) + (a2 + a3);
    __syncthreads();

    if (tid < 32) {
        float gi = sg[0][b] + sg[4][b];
        float gf = sg[1][b] + sg[5][b];
        float gg = sg[2][b] + sg[6][b];
        float go = sg[3][b] + sg[7][b];
        float c = g_c[b * DHID + col];
        c = sigfast(gf) * c + sigfast(gi) * tanhfast(gg);
        float h = sigfast(go) * tanhfast(c);
        g_c[b * DHID + col] = c;
        g_h[(t + 1) & 1][b * DHID + col] = h;
        g_xcatT[col * B + b] = h;
    }
}

// ---------------------------------------------------------------------------
// Per-step x prep: bf16 hi/lo A-fragments (ping-pong buffer) + history save.
// ---------------------------------------------------------------------------
__global__ void __launch_bounds__(128) k_xprep(int t) {
    __shared__ float xs[16][33];
    int c = blockIdx.x, tid = threadIdx.x;
    int k0 = c * 16;
    uint4* xab = g_xfragA[t & 1];

    for (int idx = tid; idx < 512; idx += 128) {
        int kl = idx >> 5, bb = idx & 31;
        int kg = k0 + kl;
        xs[kl][bb] = (kg < KFC) ? g_xcatT[kg * B + bb] : 0.0f;
    }
    __syncthreads();

    int mt = tid >> 6;
    int l = (tid >> 1) & 31;
    int part = tid & 1;
    int g = l >> 2, t4 = l & 3;
    int b0 = mt * 16 + g;

    float v00 = xs[2 * t4][b0],     v01 = xs[2 * t4 + 1][b0];
    float v10 = xs[2 * t4][b0 + 8], v11 = xs[2 * t4 + 1][b0 + 8];
    float v20 = xs[2 * t4 + 8][b0],     v21 = xs[2 * t4 + 9][b0];
    float v30 = xs[2 * t4 + 8][b0 + 8], v31 = xs[2 * t4 + 9][b0 + 8];

    __nv_bfloat16 h00, l00, h01, l01, h10, l10, h11, l11;
    __nv_bfloat16 h20, l20, h21, l21, h30, l30, h31, l31;
    split2(v00, h00, l00); split2(v01, h01, l01);
    split2(v10, h10, l10); split2(v11, h11, l11);
    split2(v20, h20, l20); split2(v21, h21, l21);
    split2(v30, h30, l30); split2(v31, h31, l31);
    uint4 o;
    if (part == 0) {
        o.x = pkbf(h00, h01); o.y = pkbf(h10, h11);
        o.z = pkbf(h20, h21); o.w = pkbf(h30, h31);
    } else {
        o.x = pkbf(l00, l01); o.y = pkbf(l10, l11);
        o.z = pkbf(l20, l21); o.w = pkbf(l30, l31);
    }
    xab[((c * 2 + mt) * 2 + part) * 32 + l] = o;

    for (int idx = tid; idx < 512; idx += 128) {
        int kg = k0 + (idx >> 5);
        int bb = idx & 31;
        if (kg < KFC)
            g_xhist[(size_t)t * (KFC * B) + kg * B + bb] = g_xcatT[kg * B + bb];
    }
}

// ---------------------------------------------------------------------------
// Per-step FC on tensor cores (mma.sync bf16, 3-term split). K=32 chunks,
// 3-stage bulkcp pipeline, A-frags double-buffered in regs. grid = 125 x 256.
// PDL: fires launch_dependents at entry so score(t+1)... overlaps this kernel.
// MMACHUNK reordered term-outer / tile-inner: each accumulator reused only
// after 8 independent mma -> HMMA latency hidden (bit-identical math).
// ---------------------------------------------------------------------------
#define FC_SMEM (3 * 32768)

#define LOADA(dst, c) do {                                                     \
    int cc0 = (c) * 2;                                                         \
    dst[0] = __ldg(&xab[((cc0 * 2 + 0) * 2 + 0) * 32 + lane]);                 \
    dst[1] = __ldg(&xab[((cc0 * 2 + 0) * 2 + 1) * 32 + lane]);                 \
    dst[2] = __ldg(&xab[((cc0 * 2 + 1) * 2 + 0) * 32 + lane]);                 \
    dst[3] = __ldg(&xab[((cc0 * 2 + 1) * 2 + 1) * 32 + lane]);                 \
    dst[4] = __ldg(&xab[(((cc0 + 1) * 2 + 0) * 2 + 0) * 32 + lane]);           \
    dst[5] = __ldg(&xab[(((cc0 + 1) * 2 + 0) * 2 + 1) * 32 + lane]);           \
    dst[6] = __ldg(&xab[(((cc0 + 1) * 2 + 1) * 2 + 0) * 32 + lane]);           \
    dst[7] = __ldg(&xab[(((cc0 + 1) * 2 + 1) * 2 + 1) * 32 + lane]);           \
} while (0)

// term-outer ordering: hh pass (8 mma), lh pass (8), hl pass (8) per ksub.
#define MMACHUNK(af, slot) do {                                                \
    _Pragma("unroll")                                                          \
    for (int ksub = 0; ksub < 2; ksub++) {                                     \
        uint4 ah0 = af[ksub * 4 + 0], al0 = af[ksub * 4 + 1];                  \
        uint4 ah1 = af[ksub * 4 + 2], al1 = af[ksub * 4 + 3];                  \
        const uint4* wbuf = swq + (slot) * 2048 + ksub * 1024 + wrp * 128;     \
        uint4 bq0 = wbuf[0 * 32 + lane];                                       \
        uint4 bq1 = wbuf[1 * 32 + lane];                                       \
        uint4 bq2 = wbuf[2 * 32 + lane];                                       \
        uint4 bq3 = wbuf[3 * 32 + lane];                                       \
        /* hh pass */                                                          \
        mma16816(acc[0][0], ah0.x, ah0.y, ah0.z, ah0.w, bq0.x, bq0.y);         \
        mma16816(acc[1][0], ah1.x, ah1.y, ah1.z, ah1.w, bq0.x, bq0.y);         \
        mma16816(acc[0][1], ah0.x, ah0.y, ah0.z, ah0.w, bq1.x, bq1.y);         \
        mma16816(acc[1][1], ah1.x, ah1.y, ah1.z, ah1.w, bq1.x, bq1.y);         \
        mma16816(acc[0][2], ah0.x, ah0.y, ah0.z, ah0.w, bq2.x, bq2.y);         \
        mma16816(acc[1][2], ah1.x, ah1.y, ah1.z, ah1.w, bq2.x, bq2.y);         \
        mma16816(acc[0][3], ah0.x, ah0.y, ah0.z, ah0.w, bq3.x, bq3.y);         \
        mma16816(acc[1][3], ah1.x, ah1.y, ah1.z, ah1.w, bq3.x, bq3.y);         \
        /* lh pass */                                                          \
        mma16816(acc[0][0], al0.x, al0.y, al0.z, al0.w, bq0.x, bq0.y);         \
        mma16816(acc[1][0], al1.x, al1.y, al1.z, al1.w, bq0.x, bq0.y);         \
        mma16816(acc[0][1], al0.x, al0.y, al0.z, al0.w, bq1.x, bq1.y);         \
        mma16816(acc[1][1], al1.x, al1.y, al1.z, al1.w, bq1.x, bq1.y);         \
        mma16816(acc[0][2], al0.x, al0.y, al0.z, al0.w, bq2.x, bq2.y);         \
        mma16816(acc[1][2], al1.x, al1.y, al1.z, al1.w, bq2.x, bq2.y);         \
        mma16816(acc[0][3], al0.x, al0.y, al0.z, al0.w, bq3.x, bq3.y);         \
        mma16816(acc[1][3], al1.x, al1.y, al1.z, al1.w, bq3.x, bq3.y);         \
        /* hl pass */                                                          \
        mma16816(acc[0][0], ah0.x, ah0.y, ah0.z, ah0.w, bq0.z, bq0.w);         \
        mma16816(acc[1][0], ah1.x, ah1.y, ah1.z, ah1.w, bq0.z, bq0.w);         \
        mma16816(acc[0][1], ah0.x, ah0.y, ah0.z, ah0.w, bq1.z, bq1.w);         \
        mma16816(acc[1][1], ah1.x, ah1.y, ah1.z, ah1.w, bq1.z, bq1.w);         \
        mma16816(acc[0][2], ah0.x, ah0.y, ah0.z, ah0.w, bq2.z, bq2.w);         \
        mma16816(acc[1][2], ah1.x, ah1.y, ah1.z, ah1.w, bq2.z, bq2.w);         \
        mma16816(acc[0][3], ah0.x, ah0.y, ah0.z, ah0.w, bq3.z, bq3.w);         \
        mma16816(acc[1][3], ah1.x, ah1.y, ah1.z, ah1.w, bq3.z, bq3.w);         \
    }                                                                          \
} while (0)

#define ISSUE(c) do {                                                          \
    int s2 = (c) % 3;                                                          \
    uint32_t sd = sb + s2 * 32768u;                                            \
    mbar_expect(mb + 8 * s2, 32768u);                                          \
    bulkcp(sd,          g_wfrag + ((size_t)(2 * (c))     * NTILES + nt0) * 32, \
           16384u, mb + 8 * s2);                                               \
    bulkcp(sd + 16384u, g_wfrag + ((size_t)(2 * (c) + 1) * NTILES + nt0) * 32, \
           16384u, mb + 8 * s2);                                               \
} while (0)

__global__ void __launch_bounds__(256) k_fc(const float* __restrict__ fc_b,
                                            float* __restrict__ outp, int t) {
    // PDL: let the next kernel (score(t+1)) launch immediately
    asm volatile("griddepcontrol.launch_dependents;" ::: "memory");

    extern __shared__ __align__(16) uint4 swq[];          // 3 x 32KB
    __shared__ __align__(8) unsigned long long mbar_st[3];
    int tid = threadIdx.x;
    int lane = tid & 31, wrp = tid >> 5;
    int n0 = blockIdx.x * 256;
    int nt0 = blockIdx.x * 32;
    const uint4* xab = g_xfragA[t & 1];

    uint32_t sb = (uint32_t)__cvta_generic_to_shared(&swq[0]);
    uint32_t mb = (uint32_t)__cvta_generic_to_shared(&mbar_st[0]);

    if (tid == 0) {
#pragma unroll
        for (int s = 0; s < 3; s++) mbar_init(mb + 8 * s, 1);
    }
    __syncthreads();
    if (tid == 0) { ISSUE(0); ISSUE(1); }

    float acc[2][4][4];
#pragma unroll
    for (int m = 0; m < 2; m++)
#pragma unroll
        for (int i = 0; i < 4; i++)
#pragma unroll
            for (int j = 0; j < 4; j++) acc[m][i][j] = 0.0f;

    uint4 afA[8], afB[8];
    LOADA(afA, 0);

    for (int c = 0; c < NCH32; c += 2) {
        if (c + 1 < NCH32) LOADA(afB, c + 1);
        mbar_wait(mb + 8 * (c % 3), (uint32_t)((c / 3) & 1));
        MMACHUNK(afA, c % 3);
        __syncthreads();
        if (tid == 0 && c + 2 < NCH32) ISSUE(c + 2);

        if (c + 1 < NCH32) {
            if (c + 2 < NCH32) LOADA(afA, c + 2);
            mbar_wait(mb + 8 * ((c + 1) % 3), (uint32_t)(((c + 1) / 3) & 1));
            MMACHUNK(afB, (c + 1) % 3);
            __syncthreads();
            if (tid == 0 && c + 3 < NCH32) ISSUE(c + 3);
        }
    }

    int g = lane >> 2, t4 = lane & 3;
#pragma unroll
    for (int m = 0; m < 2; m++) {
#pragma unroll
        for (int i = 0; i < 4; i++) {
            int n = n0 + (wrp * 4 + i) * 8 + 2 * t4;
            float b0 = fc_b[n], b1 = fc_b[n + 1];
            int br = m * 16 + g;
            size_t o1 = ((size_t)br * TT + (t + 1)) * VOC + n;
            size_t o2 = ((size_t)(br + 8) * TT + (t + 1)) * VOC + n;
            outp[o1]     = acc[m][i][0] + b0;
            outp[o1 + 1] = acc[m][i][1] + b1;
            outp[o2]     = acc[m][i][2] + b0;
            outp[o2 + 1] = acc[m][i][3] + b1;
        }
    }
}

// ---------------------------------------------------------------------------
// Epilogue argmax: approx top-2 scan + exact fp32 recompute of candidates.
// ---------------------------------------------------------------------------
__global__ void __launch_bounds__(256) k_argmax(const float* __restrict__ outp,
                                                const float* __restrict__ fc_W,
                                                const float* __restrict__ fc_b,
                                                float* __restrict__ tokout) {
    int row = blockIdx.x;
    int b = row / TT, tt = row % TT;
    int tid = threadIdx.x;
    if (tt == 0) { if (tid == 0) tokout[row] = 0.0f; return; }

    const float* p = outp + ((size_t)b * TT + tt) * VOC;
    __shared__ float sv[256];
    __shared__ int si[256];
    __shared__ float dre[2];

    float best = -1e30f; int bi = 0;
    for (int i = tid; i < VOC; i += 256) {
        float v = p[i];
        if (v > best) { best = v; bi = i; }
    }
    sv[tid] = best; si[tid] = bi;
    __syncthreads();
    for (int off = 128; off > 0; off >>= 1) {
        if (tid < off) {
            if (sv[tid + off] > sv[tid] ||
                (sv[tid + off] == sv[tid] && si[tid + off] < si[tid])) {
                sv[tid] = sv[tid + off]; si[tid] = si[tid + off];
            }
        }
        __syncthreads();
    }
    int i1 = si[0];
    __syncthreads();

    best = -1e30f; bi = 0;
    for (int i = tid; i < VOC; i += 256) {
        if (i == i1) continue;
        float v = p[i];
        if (v > best) { best = v; bi = i; }
    }
    sv[tid] = best; si[tid] = bi;
    __syncthreads();
    for (int off = 128; off > 0; off >>= 1) {
        if (tid < off) {
            if (sv[tid + off] > sv[tid] ||
                (sv[tid + off] == sv[tid] && si[tid + off] < si[tid])) {
                sv[tid] = sv[tid + off]; si[tid] = si[tid + off];
            }
        }
        __syncthreads();
    }
    int i2 = si[0];
    __syncthreads();

    int wrp = tid >> 5, lane = tid & 31;
    if (wrp < 2) {
        int idx = (wrp == 0) ? i1 : i2;
        const float* wr = fc_W + (size_t)idx * KFC;
        const float* xr = g_xhist + (size_t)(tt - 1) * (KFC * B);
        float a = 0.0f;
        for (int k = lane; k < KFC; k += 32)
            a = fmaf(xr[k * B + b], wr[k], a);
#pragma unroll
        for (int o = 16; o > 0; o >>= 1)
            a += __shfl_xor_sync(0xFFFFFFFFu, a, o);
        if (lane == 0) dre[wrp] = a + fc_b[idx];
    }
    __syncthreads();
    if (tid == 0) {
        float d1 = dre[0], d2 = dre[1];
        int winner = i1;
        if (d2 > d1 || (d2 == d1 && i2 < i1)) winner = i2;
        tokout[row] = (float)winner;
    }
}

// ---------------------------------------------------------------------------
extern "C" void kernel_launch(void* const* d_in, const int* in_sizes, int n_in,
                              void* d_out, int out_size) {
    const float* enc    = (const float*)d_in[0];
    const int*   trg    = (const int*)d_in[1];
    const float* embt   = (const float*)d_in[2];
    const float* attn_W = (const float*)d_in[3];
    const float* attn_b = (const float*)d_in[4];
    const float* attn_v = (const float*)d_in[5];
    const float* W_ih   = (const float*)d_in[6];
    const float* W_hh   = (const float*)d_in[7];
    const float* b_ih   = (const float*)d_in[8];
    const float* b_hh   = (const float*)d_in[9];
    const float* fc_W   = (const float*)d_in[10];
    const float* fc_b   = (const float*)d_in[11];
    float* outp = (float*)d_out;
    (void)in_sizes; (void)n_in;

    cudaFuncSetAttribute(k_fc, cudaFuncAttributeMaxDynamicSharedMemorySize, FC_SMEM);

    k_init<<<(B * VOC + 255) / 256, 256>>>(outp);
    k_wprep<<<dim3(NTILES / 8, NCH16), 256>>>(fc_W);
    k_encproj<<<(B * S) / 32, 128>>>(enc, attn_W, attn_b);

    for (int t = 0; t < NSTEP; t++) {
        if (t == 0) {
            k_score2<<<dim3(16, B), 128>>>(trg, embt, attn_W, attn_v, t);
        } else {
            cudaLaunchConfig_t cfg = {};
            cfg.gridDim = dim3(16, B, 1);
            cfg.blockDim = dim3(128, 1, 1);
            cfg.dynamicSmemBytes = 0;
            cfg.stream = 0;
            cudaLaunchAttribute at[1];
            at[0].id = cudaLaunchAttributeProgrammaticStreamSerialization;
            at[0].val.programmaticStreamSerializationAllowed = 1;
            cfg.attrs = at;
            cfg.numAttrs = 1;
            cudaLaunchKernelEx(&cfg, k_score2, trg, embt, attn_W, attn_v, t);
        }
        k_ctx<<<dim3(EHID / 128, B), 128>>>(enc);
        k_lstm<<<DHID, 256>>>(W_ih, W_hh, b_ih, b_hh, t);
        k_xprep<<<NCH16, 128>>>(t);
        k_fc<<<VOC / 256, 256, FC_SMEM>>>(fc_b, outp, t);
    }

    long long need = (long long)B * TT * VOC + (long long)B * TT;
    if ((long long)out_size >= need) {
        k_argmax<<<B * TT, 256>>>(outp, fc_W, fc_b,
                                  outp + (size_t)B * TT * VOC);
    }
}

// round 17
// speedup vs baseline: 1.1665x; 1.1483x over previous
#include <cuda_runtime.h>
#include <cuda_bf16.h>
#include <cuda_fp16.h>
#include <math.h>
#include <stdint.h>

// Problem dims
#define B 32
#define S 256
#define EHID 768
#define DHID 128
#define EMBD 200
#define VOC 32000
#define TT 96
#define NSTEP 95
#define KFC 1096    // DHID + EHID + EMBD
#define KLSTM 968   // EMBD + EHID
#define NCH16 70    // k-chunks of 16 (padded)
#define NCH32 35    // k-chunks of 32
#define NTILES 4000 // VOC/8 n-tiles of 8

// Scratch (static device globals: allowed; no runtime allocation)
__device__ uint2  g_wfrag[(size_t)NCH16 * NTILES * 32]; // fp16 HI-only B-frags, ~72MB
__device__ uint4  g_xfragA[2][NCH16 * 2 * 2 * 32];      // fp16 hi/lo A-frags, ping-pong
__device__ float  g_enc_proj[B * S * DHID];
__device__ float  g_xcatT[KFC * B];
__device__ float  g_xhist[NSTEP * KFC * B];             // fp32 history for exact argmax
__device__ float  g_scr[B * S];
__device__ float  g_h[2][B * DHID];
__device__ float  g_c[B * DHID];

// fast activations (validated across rounds)
__device__ __forceinline__ float sigfast(float x) {
    return __fdividef(1.0f, 1.0f + __expf(-x));
}
__device__ __forceinline__ float tanhfast(float x) {
    x = fminf(fmaxf(x, -15.0f), 15.0f);
    float e = __expf(2.0f * x);
    return __fdividef(e - 1.0f, e + 1.0f);
}

// mbarrier + bulk-copy helpers (proven R10-R16)
__device__ __forceinline__ void mbar_init(uint32_t a, uint32_t cnt) {
    asm volatile("mbarrier.init.shared.b64 [%0], %1;" :: "r"(a), "r"(cnt) : "memory");
}
__device__ __forceinline__ void mbar_expect(uint32_t a, uint32_t bytes) {
    asm volatile("mbarrier.arrive.expect_tx.shared.b64 _, [%0], %1;"
                 :: "r"(a), "r"(bytes) : "memory");
}
__device__ __forceinline__ void mbar_wait(uint32_t a, uint32_t parity) {
    uint32_t done;
    asm volatile(
        "{\n\t.reg .pred p;\n\t"
        "mbarrier.try_wait.parity.acquire.cta.shared::cta.b64 p, [%1], %2;\n\t"
        "selp.b32 %0, 1, 0, p;\n\t}"
        : "=r"(done) : "r"(a), "r"(parity) : "memory");
    if (!done) {
        asm volatile(
            "{\n\t.reg .pred P1;\n\t"
            "W_%=:\n\t"
            "mbarrier.try_wait.parity.acquire.cta.shared::cta.b64 P1, [%0], %1, 0x989680;\n\t"
            "@P1 bra.uni D_%=;\n\t"
            "bra.uni W_%=;\n\t"
            "D_%=:\n\t}"
            :: "r"(a), "r"(parity) : "memory");
    }
}
__device__ __forceinline__ void bulkcp(uint32_t dst, const void* src, uint32_t bytes,
                                       uint32_t mbar) {
    asm volatile(
        "cp.async.bulk.shared::cluster.global.mbarrier::complete_tx::bytes "
        "[%0], [%1], %2, [%3];"
        :: "r"(dst), "l"(src), "r"(bytes), "r"(mbar) : "memory");
}

// fp16 pack/split
__device__ __forceinline__ uint32_t pkh(__half a, __half b) {
    uint32_t lo = (uint32_t)__half_as_ushort(a);
    uint32_t hi = (uint32_t)__half_as_ushort(b);
    return lo | (hi << 16);
}
__device__ __forceinline__ void split2h(float v, __half& h, __half& l) {
    h = __float2half_rn(v);
    l = __float2half_rn(v - __half2float(h));
}

// warp-level fp16 tensor-core mma, m16n8k16, fp32 accumulate
__device__ __forceinline__ void mma16816h(float* d, uint32_t a0, uint32_t a1,
                                          uint32_t a2, uint32_t a3,
                                          uint32_t b0, uint32_t b1) {
    asm volatile(
        "mma.sync.aligned.m16n8k16.row.col.f32.f16.f16.f32 "
        "{%0,%1,%2,%3}, {%4,%5,%6,%7}, {%8,%9}, {%0,%1,%2,%3};"
        : "+f"(d[0]), "+f"(d[1]), "+f"(d[2]), "+f"(d[3])
        : "r"(a0), "r"(a1), "r"(a2), "r"(a3), "r"(b0), "r"(b1));
}

// ---------------------------------------------------------------------------
__global__ void k_init(float* __restrict__ outp) {
    int i = blockIdx.x * blockDim.x + threadIdx.x;
    if (i < B * VOC) {
        int b = i / VOC, v = i % VOC;
        outp[(size_t)b * TT * VOC + v] = 0.0f;
    }
    if (i < B * DHID) { g_h[0][i] = 0.0f; g_h[1][i] = 0.0f; g_c[i] = 0.0f; }
}

// ---------------------------------------------------------------------------
// Repack fc_W [VOC][KFC] into fp16 HI-only B-fragments (fragment-ordered). Once.
// ---------------------------------------------------------------------------
__global__ void __launch_bounds__(256) k_wprep(const float* __restrict__ W) {
    __shared__ float ws[64][17];
    int c = blockIdx.y, ng = blockIdx.x;
    int k0 = c * 16, n0g = ng * 64;
    int tid = threadIdx.x;

    for (int idx = tid; idx < 64 * 16; idx += 256) {
        int r = idx >> 4, q = idx & 15;
        int kg = k0 + q;
        ws[r][q] = (kg < KFC) ? W[(size_t)(n0g + r) * KFC + kg] : 0.0f;
    }
    __syncthreads();

    int ntl = tid >> 5;
    int l = tid & 31;
    int g = l >> 2, t4 = l & 3;
    int nr = ntl * 8 + g;
    __half h0 = __float2half_rn(ws[nr][2 * t4]);
    __half h1 = __float2half_rn(ws[nr][2 * t4 + 1]);
    __half h2 = __float2half_rn(ws[nr][2 * t4 + 8]);
    __half h3 = __float2half_rn(ws[nr][2 * t4 + 9]);
    uint2 o;
    o.x = pkh(h0, h1); o.y = pkh(h2, h3);
    int nt = ng * 8 + ntl;
    g_wfrag[((size_t)c * NTILES + nt) * 32 + l] = o;
}

// ---------------------------------------------------------------------------
// enc_proj (once)
// ---------------------------------------------------------------------------
__global__ void __launch_bounds__(128) k_encproj(const float* __restrict__ enc,
                                                 const float* __restrict__ attn_W,
                                                 const float* __restrict__ attn_b) {
    __shared__ __align__(16) float es[32 * 8];
    int j = threadIdx.x;
    int row0 = blockIdx.x * 32;
    float acc[32];
    float bj = attn_b[j];
#pragma unroll
    for (int r = 0; r < 32; r++) acc[r] = bj;
    const float* Wenc = attn_W + DHID * DHID;

    for (int k0 = 0; k0 < EHID; k0 += 8) {
        __syncthreads();
        int i0 = j;
        es[i0] = enc[(size_t)(row0 + (i0 >> 3)) * EHID + k0 + (i0 & 7)];
        int i1 = j + 128;
        es[i1] = enc[(size_t)(row0 + (i1 >> 3)) * EHID + k0 + (i1 & 7)];
        __syncthreads();
        float w[8];
#pragma unroll
        for (int kk = 0; kk < 8; kk++) w[kk] = Wenc[(size_t)(k0 + kk) * DHID + j];
#pragma unroll
        for (int r = 0; r < 32; r++) {
            const float4* e4 = (const float4*)(es + r * 8);
            float4 e0 = e4[0], e1 = e4[1];
            acc[r] = fmaf(e0.x, w[0], acc[r]); acc[r] = fmaf(e0.y, w[1], acc[r]);
            acc[r] = fmaf(e0.z, w[2], acc[r]); acc[r] = fmaf(e0.w, w[3], acc[r]);
            acc[r] = fmaf(e1.x, w[4], acc[r]); acc[r] = fmaf(e1.y, w[5], acc[r]);
            acc[r] = fmaf(e1.z, w[6], acc[r]); acc[r] = fmaf(e1.w, w[7], acc[r]);
        }
    }
#pragma unroll
    for (int r = 0; r < 32; r++)
        g_enc_proj[(size_t)(row0 + r) * DHID + j] = acc[r];
}

// ---------------------------------------------------------------------------
// Per-step raw scores: grid (16, B) = 512 blocks, 128 threads.
// ---------------------------------------------------------------------------
__global__ void __launch_bounds__(128) k_score2(
    const int* __restrict__ trg, const float* __restrict__ embt,
    const float* __restrict__ attn_W, const float* __restrict__ attn_v, int t)
{
    int sb = blockIdx.x, b = blockIdx.y;
    int tid = threadIdx.x;
    __shared__ float sh_h[DHID], sh_hp[DHID], sh_v[DHID];

    sh_h[tid] = g_h[t & 1][b * DHID + tid];
    sh_v[tid] = attn_v[tid];
    __syncthreads();

    {
        float a0 = 0.f, a1 = 0.f, a2 = 0.f, a3 = 0.f;
#pragma unroll 8
        for (int k = 0; k < DHID; k += 4) {
            a0 = fmaf(sh_h[k],     attn_W[(k)     * DHID + tid], a0);
            a1 = fmaf(sh_h[k + 1], attn_W[(k + 1) * DHID + tid], a1);
            a2 = fmaf(sh_h[k + 2], attn_W[(k + 2) * DHID + tid], a2);
            a3 = fmaf(sh_h[k + 3], attn_W[(k + 3) * DHID + tid], a3);
        }
        sh_hp[tid] = (a0 + a1) + (a2 + a3);
    }
    __syncthreads();

    int w = tid >> 5, lane = tid & 31;
    const float* epb = g_enc_proj + (size_t)b * S * DHID;
    float hp0 = sh_hp[lane],      hp1 = sh_hp[lane + 32];
    float hp2 = sh_hp[lane + 64], hp3 = sh_hp[lane + 96];
    float v0 = sh_v[lane],        v1 = sh_v[lane + 32];
    float v2 = sh_v[lane + 64],   v3 = sh_v[lane + 96];
#pragma unroll
    for (int i = 0; i < 4; i++) {
        int s = sb * 16 + w * 4 + i;
        const float* ep = epb + (size_t)s * DHID;
        float acc = tanhfast(ep[lane]      + hp0) * v0
                  + tanhfast(ep[lane + 32] + hp1) * v1
                  + tanhfast(ep[lane + 64] + hp2) * v2
                  + tanhfast(ep[lane + 96] + hp3) * v3;
#pragma unroll
        for (int o = 16; o > 0; o >>= 1)
            acc += __shfl_xor_sync(0xFFFFFFFFu, acc, o);
        if (lane == 0) g_scr[b * S + s] = acc;
    }

    if (sb == 0) {
        int tok = trg[b * TT + t];
        for (int d = tid; d < EMBD; d += 128)
            g_xcatT[(DHID + EHID + d) * B + b] = embt[(size_t)tok * EMBD + d];
    }
}

// ---------------------------------------------------------------------------
// Per-step context with fused softmax: grid (6, 32), 128 threads.
// ---------------------------------------------------------------------------
__global__ void __launch_bounds__(128) k_ctx(const float* __restrict__ enc) {
    int tid = threadIdx.x;
    int d = blockIdx.x * 128 + tid;
    int b = blockIdx.y;
    __shared__ float sa[S];
    __shared__ float red[128];

    float r0 = g_scr[b * S + tid], r1 = g_scr[b * S + tid + 128];
    red[tid] = fmaxf(r0, r1);
    __syncthreads();
    for (int off = 64; off > 0; off >>= 1) {
        if (tid < off) red[tid] = fmaxf(red[tid], red[tid + off]);
        __syncthreads();
    }
    float mx = red[0];
    __syncthreads();
    float e0 = __expf(r0 - mx), e1 = __expf(r1 - mx);
    red[tid] = e0 + e1;
    __syncthreads();
    for (int off = 64; off > 0; off >>= 1) {
        if (tid < off) red[tid] += red[tid + off];
        __syncthreads();
    }
    float inv = __fdividef(1.0f, red[0]);
    sa[tid] = e0 * inv;
    sa[tid + 128] = e1 * inv;
    __syncthreads();

    const float* e = enc + (size_t)b * S * EHID + d;
    float a[8];
#pragma unroll
    for (int j = 0; j < 8; j++) a[j] = 0.0f;
#pragma unroll 4
    for (int s = 0; s < S; s += 8) {
#pragma unroll
        for (int j = 0; j < 8; j++)
            a[j] = fmaf(sa[s + j], e[(size_t)(s + j) * EHID], a[j]);
    }
    float r = ((a[0] + a[1]) + (a[2] + a[3])) + ((a[4] + a[5]) + (a[6] + a[7]));
    g_xcatT[(DHID + d) * B + b] = r;
}

// ---------------------------------------------------------------------------
// Per-step LSTM, 2-way k-split: grid = 128 blocks, 256 threads.
// ---------------------------------------------------------------------------
__global__ void __launch_bounds__(256) k_lstm(
    const float* __restrict__ W_ih, const float* __restrict__ W_hh,
    const float* __restrict__ b_ih, const float* __restrict__ b_hh, int t)
{
    int col = blockIdx.x;
    int tid = threadIdx.x;
    int half = tid >> 7;
    int gate = (tid >> 5) & 3;
    int b = tid & 31;
    int g = gate * DHID + col;

    __shared__ float sh_hold[32 * 129];
    __shared__ float sg[8][32];

    const float* hold = g_h[t & 1];
    for (int i = tid; i < B * DHID; i += 256)
        sh_hold[(i >> 7) * 129 + (i & 127)] = hold[i];
    __syncthreads();

    const float* Wg = W_ih + (size_t)g * KLSTM;
    float a0 = 0.f, a1 = 0.f, a2 = 0.f, a3 = 0.f;
    if (half == 0) {
        a0 = b_ih[g] + b_hh[g];
        const float* xe = g_xcatT + 896 * B + b;
#pragma unroll 2
        for (int k = 0; k < 200; k += 4) {
            float4 w = *(const float4*)(Wg + k);
            a0 = fmaf(w.x, xe[(k + 0) * B], a0);
            a1 = fmaf(w.y, xe[(k + 1) * B], a1);
            a2 = fmaf(w.z, xe[(k + 2) * B], a2);
            a3 = fmaf(w.w, xe[(k + 3) * B], a3);
        }
        const float* xw = g_xcatT - 72 * B + b;
#pragma unroll 2
        for (int k = 200; k < 484; k += 4) {
            float4 w = *(const float4*)(Wg + k);
            a0 = fmaf(w.x, xw[(k + 0) * B], a0);
            a1 = fmaf(w.y, xw[(k + 1) * B], a1);
            a2 = fmaf(w.z, xw[(k + 2) * B], a2);
            a3 = fmaf(w.w, xw[(k + 3) * B], a3);
        }
    } else {
        const float* xw = g_xcatT - 72 * B + b;
#pragma unroll 2
        for (int k = 484; k < 968; k += 4) {
            float4 w = *(const float4*)(Wg + k);
            a0 = fmaf(w.x, xw[(k + 0) * B], a0);
            a1 = fmaf(w.y, xw[(k + 1) * B], a1);
            a2 = fmaf(w.z, xw[(k + 2) * B], a2);
            a3 = fmaf(w.w, xw[(k + 3) * B], a3);
        }
        const float* Wh = W_hh + (size_t)g * DHID;
        const float* hb = sh_hold + b * 129;
#pragma unroll 4
        for (int k = 0; k < DHID; k += 4) {
            float4 w = *(const float4*)(Wh + k);
            a0 = fmaf(w.x, hb[k + 0], a0);
            a1 = fmaf(w.y, hb[k + 1], a1);
            a2 = fmaf(w.z, hb[k + 2], a2);
            a3 = fmaf(w.w, hb[k + 3], a3);
        }
    }
    sg[half * 4 + gate][b] = (a0 + a1) + (a2 + a3);
    __syncthreads();

    if (tid < 32) {
        float gi = sg[0][b] + sg[4][b];
        float gf = sg[1][b] + sg[5][b];
        float gg = sg[2][b] + sg[6][b];
        float go = sg[3][b] + sg[7][b];
        float c = g_c[b * DHID + col];
        c = sigfast(gf) * c + sigfast(gi) * tanhfast(gg);
        float h = sigfast(go) * tanhfast(c);
        g_c[b * DHID + col] = c;
        g_h[(t + 1) & 1][b * DHID + col] = h;
        g_xcatT[col * B + b] = h;
    }
}

// ---------------------------------------------------------------------------
// Per-step x prep: fp16 hi/lo A-fragments (ping-pong buffer) + history save.
// ---------------------------------------------------------------------------
__global__ void __launch_bounds__(128) k_xprep(int t) {
    __shared__ float xs[16][33];
    int c = blockIdx.x, tid = threadIdx.x;
    int k0 = c * 16;
    uint4* xab = g_xfragA[t & 1];

    for (int idx = tid; idx < 512; idx += 128) {
        int kl = idx >> 5, bb = idx & 31;
        int kg = k0 + kl;
        xs[kl][bb] = (kg < KFC) ? g_xcatT[kg * B + bb] : 0.0f;
    }
    __syncthreads();

    int mt = tid >> 6;
    int l = (tid >> 1) & 31;
    int part = tid & 1;
    int g = l >> 2, t4 = l & 3;
    int b0 = mt * 16 + g;

    float v00 = xs[2 * t4][b0],     v01 = xs[2 * t4 + 1][b0];
    float v10 = xs[2 * t4][b0 + 8], v11 = xs[2 * t4 + 1][b0 + 8];
    float v20 = xs[2 * t4 + 8][b0],     v21 = xs[2 * t4 + 9][b0];
    float v30 = xs[2 * t4 + 8][b0 + 8], v31 = xs[2 * t4 + 9][b0 + 8];

    __half h00, l00, h01, l01, h10, l10, h11, l11;
    __half h20, l20, h21, l21, h30, l30, h31, l31;
    split2h(v00, h00, l00); split2h(v01, h01, l01);
    split2h(v10, h10, l10); split2h(v11, h11, l11);
    split2h(v20, h20, l20); split2h(v21, h21, l21);
    split2h(v30, h30, l30); split2h(v31, h31, l31);
    uint4 o;
    if (part == 0) {
        o.x = pkh(h00, h01); o.y = pkh(h10, h11);
        o.z = pkh(h20, h21); o.w = pkh(h30, h31);
    } else {
        o.x = pkh(l00, l01); o.y = pkh(l10, l11);
        o.z = pkh(l20, l21); o.w = pkh(l30, l31);
    }
    xab[((c * 2 + mt) * 2 + part) * 32 + l] = o;

    for (int idx = tid; idx < 512; idx += 128) {
        int kg = k0 + (idx >> 5);
        int bb = idx & 31;
        if (kg < KFC)
            g_xhist[(size_t)t * (KFC * B) + kg * B + bb] = g_xcatT[kg * B + bb];
    }
}

// ---------------------------------------------------------------------------
// Per-step FC on tensor cores (mma.sync fp16, 2-term split: xh@wh + xl@wh).
// K=32 chunks, 4-stage bulkcp pipeline (16KB stages), A-frags double-buffered.
// grid = 125 x 256. PDL fires so score(t+1) overlaps. -33% mma vs R13.
// ---------------------------------------------------------------------------
#define FC_SMEM (4 * 16384)

#define LOADA(dst, c) do {                                                     \
    int cc0 = (c) * 2;                                                         \
    dst[0] = __ldg(&xab[((cc0 * 2 + 0) * 2 + 0) * 32 + lane]);                 \
    dst[1] = __ldg(&xab[((cc0 * 2 + 0) * 2 + 1) * 32 + lane]);                 \
    dst[2] = __ldg(&xab[((cc0 * 2 + 1) * 2 + 0) * 32 + lane]);                 \
    dst[3] = __ldg(&xab[((cc0 * 2 + 1) * 2 + 1) * 32 + lane]);                 \
    dst[4] = __ldg(&xab[(((cc0 + 1) * 2 + 0) * 2 + 0) * 32 + lane]);           \
    dst[5] = __ldg(&xab[(((cc0 + 1) * 2 + 0) * 2 + 1) * 32 + lane]);           \
    dst[6] = __ldg(&xab[(((cc0 + 1) * 2 + 1) * 2 + 0) * 32 + lane]);           \
    dst[7] = __ldg(&xab[(((cc0 + 1) * 2 + 1) * 2 + 1) * 32 + lane]);           \
} while (0)

// 2-term: hh pass (8 mma) + lh pass (8 mma) per ksub. 32 mma per chunk32.
#define MMACHUNK(af, slot) do {                                                \
    _Pragma("unroll")                                                          \
    for (int ksub = 0; ksub < 2; ksub++) {                                     \
        uint4 ah0 = af[ksub * 4 + 0], al0 = af[ksub * 4 + 1];                  \
        uint4 ah1 = af[ksub * 4 + 2], al1 = af[ksub * 4 + 3];                  \
        const uint2* wbuf = swq + (slot) * 2048 + ksub * 1024 + wrp * 128;     \
        uint2 bq0 = wbuf[0 * 32 + lane];                                       \
        uint2 bq1 = wbuf[1 * 32 + lane];                                       \
        uint2 bq2 = wbuf[2 * 32 + lane];                                       \
        uint2 bq3 = wbuf[3 * 32 + lane];                                       \
        mma16816h(acc[0][0], ah0.x, ah0.y, ah0.z, ah0.w, bq0.x, bq0.y);        \
        mma16816h(acc[1][0], ah1.x, ah1.y, ah1.z, ah1.w, bq0.x, bq0.y);        \
        mma16816h(acc[0][1], ah0.x, ah0.y, ah0.z, ah0.w, bq1.x, bq1.y);        \
        mma16816h(acc[1][1], ah1.x, ah1.y, ah1.z, ah1.w, bq1.x, bq1.y);        \
        mma16816h(acc[0][2], ah0.x, ah0.y, ah0.z, ah0.w, bq2.x, bq2.y);        \
        mma16816h(acc[1][2], ah1.x, ah1.y, ah1.z, ah1.w, bq2.x, bq2.y);        \
        mma16816h(acc[0][3], ah0.x, ah0.y, ah0.z, ah0.w, bq3.x, bq3.y);        \
        mma16816h(acc[1][3], ah1.x, ah1.y, ah1.z, ah1.w, bq3.x, bq3.y);        \
        mma16816h(acc[0][0], al0.x, al0.y, al0.z, al0.w, bq0.x, bq0.y);        \
        mma16816h(acc[1][0], al1.x, al1.y, al1.z, al1.w, bq0.x, bq0.y);        \
        mma16816h(acc[0][1], al0.x, al0.y, al0.z, al0.w, bq1.x, bq1.y);        \
        mma16816h(acc[1][1], al1.x, al1.y, al1.z, al1.w, bq1.x, bq1.y);        \
        mma16816h(acc[0][2], al0.x, al0.y, al0.z, al0.w, bq2.x, bq2.y);        \
        mma16816h(acc[1][2], al1.x, al1.y, al1.z, al1.w, bq2.x, bq2.y);        \
        mma16816h(acc[0][3], al0.x, al0.y, al0.z, al0.w, bq3.x, bq3.y);        \
        mma16816h(acc[1][3], al1.x, al1.y, al1.z, al1.w, bq3.x, bq3.y);        \
    }                                                                          \
} while (0)

#define ISSUE(c) do {                                                          \
    int s2 = (c) & 3;                                                          \
    uint32_t sd = sb + s2 * 16384u;                                            \
    mbar_expect(mb + 8 * s2, 16384u);                                          \
    bulkcp(sd,         g_wfrag + ((size_t)(2 * (c))     * NTILES + nt0) * 32,  \
           8192u, mb + 8 * s2);                                                \
    bulkcp(sd + 8192u, g_wfrag + ((size_t)(2 * (c) + 1) * NTILES + nt0) * 32,  \
           8192u, mb + 8 * s2);                                                \
} while (0)

__global__ void __launch_bounds__(256) k_fc(const float* __restrict__ fc_b,
                                            float* __restrict__ outp, int t) {
    // PDL: let the next kernel (score(t+1)) launch immediately
    asm volatile("griddepcontrol.launch_dependents;" ::: "memory");

    extern __shared__ __align__(16) uint2 swq[];          // 4 x 16KB
    __shared__ __align__(8) unsigned long long mbar_st[4];
    int tid = threadIdx.x;
    int lane = tid & 31, wrp = tid >> 5;
    int n0 = blockIdx.x * 256;
    int nt0 = blockIdx.x * 32;
    const uint4* xab = g_xfragA[t & 1];

    uint32_t sb = (uint32_t)__cvta_generic_to_shared(&swq[0]);
    uint32_t mb = (uint32_t)__cvta_generic_to_shared(&mbar_st[0]);

    if (tid == 0) {
#pragma unroll
        for (int s = 0; s < 4; s++) mbar_init(mb + 8 * s, 1);
    }
    __syncthreads();
    if (tid == 0) { ISSUE(0); ISSUE(1); ISSUE(2); }

    float acc[2][4][4];
#pragma unroll
    for (int m = 0; m < 2; m++)
#pragma unroll
        for (int i = 0; i < 4; i++)
#pragma unroll
            for (int j = 0; j < 4; j++) acc[m][i][j] = 0.0f;

    uint4 afA[8], afB[8];
    LOADA(afA, 0);

    for (int c = 0; c < NCH32; c += 2) {
        if (c + 1 < NCH32) LOADA(afB, c + 1);
        mbar_wait(mb + 8 * (c & 3), (uint32_t)((c >> 2) & 1));
        MMACHUNK(afA, c & 3);
        __syncthreads();
        if (tid == 0 && c + 3 < NCH32) ISSUE(c + 3);

        if (c + 1 < NCH32) {
            if (c + 2 < NCH32) LOADA(afA, c + 2);
            mbar_wait(mb + 8 * ((c + 1) & 3), (uint32_t)(((c + 1) >> 2) & 1));
            MMACHUNK(afB, (c + 1) & 3);
            __syncthreads();
            if (tid == 0 && c + 4 < NCH32) ISSUE(c + 4);
        }
    }

    int g = lane >> 2, t4 = lane & 3;
#pragma unroll
    for (int m = 0; m < 2; m++) {
#pragma unroll
        for (int i = 0; i < 4; i++) {
            int n = n0 + (wrp * 4 + i) * 8 + 2 * t4;
            float b0 = fc_b[n], b1 = fc_b[n + 1];
            int br = m * 16 + g;
            size_t o1 = ((size_t)br * TT + (t + 1)) * VOC + n;
            size_t o2 = ((size_t)(br + 8) * TT + (t + 1)) * VOC + n;
            outp[o1]     = acc[m][i][0] + b0;
            outp[o1 + 1] = acc[m][i][1] + b1;
            outp[o2]     = acc[m][i][2] + b0;
            outp[o2 + 1] = acc[m][i][3] + b1;
        }
    }
}

// ---------------------------------------------------------------------------
// Epilogue argmax: approx top-2 scan + exact fp32 recompute of candidates.
// ---------------------------------------------------------------------------
__global__ void __launch_bounds__(256) k_argmax(const float* __restrict__ outp,
                                                const float* __restrict__ fc_W,
                                                const float* __restrict__ fc_b,
                                                float* __restrict__ tokout) {
    int row = blockIdx.x;
    int b = row / TT, tt = row % TT;
    int tid = threadIdx.x;
    if (tt == 0) { if (tid == 0) tokout[row] = 0.0f; return; }

    const float* p = outp + ((size_t)b * TT + tt) * VOC;
    __shared__ float sv[256];
    __shared__ int si[256];
    __shared__ float dre[2];

    float best = -1e30f; int bi = 0;
    for (int i = tid; i < VOC; i += 256) {
        float v = p[i];
        if (v > best) { best = v; bi = i; }
    }
    sv[tid] = best; si[tid] = bi;
    __syncthreads();
    for (int off = 128; off > 0; off >>= 1) {
        if (tid < off) {
            if (sv[tid + off] > sv[tid] ||
                (sv[tid + off] == sv[tid] && si[tid + off] < si[tid])) {
                sv[tid] = sv[tid + off]; si[tid] = si[tid + off];
            }
        }
        __syncthreads();
    }
    int i1 = si[0];
    __syncthreads();

    best = -1e30f; bi = 0;
    for (int i = tid; i < VOC; i += 256) {
        if (i == i1) continue;
        float v = p[i];
        if (v > best) { best = v; bi = i; }
    }
    sv[tid] = best; si[tid] = bi;
    __syncthreads();
    for (int off = 128; off > 0; off >>= 1) {
        if (tid < off) {
            if (sv[tid + off] > sv[tid] ||
                (sv[tid + off] == sv[tid] && si[tid + off] < si[tid])) {
                sv[tid] = sv[tid + off]; si[tid] = si[tid + off];
            }
        }
        __syncthreads();
    }
    int i2 = si[0];
    __syncthreads();

    int wrp = tid >> 5, lane = tid & 31;
    if (wrp < 2) {
        int idx = (wrp == 0) ? i1 : i2;
        const float* wr = fc_W + (size_t)idx * KFC;
        const float* xr = g_xhist + (size_t)(tt - 1) * (KFC * B);
        float a = 0.0f;
        for (int k = lane; k < KFC; k += 32)
            a = fmaf(xr[k * B + b], wr[k], a);
#pragma unroll
        for (int o = 16; o > 0; o >>= 1)
            a += __shfl_xor_sync(0xFFFFFFFFu, a, o);
        if (lane == 0) dre[wrp] = a + fc_b[idx];
    }
    __syncthreads();
    if (tid == 0) {
        float d1 = dre[0], d2 = dre[1];
        int winner = i1;
        if (d2 > d1 || (d2 == d1 && i2 < i1)) winner = i2;
        tokout[row] = (float)winner;
    }
}

// ---------------------------------------------------------------------------
extern "C" void kernel_launch(void* const* d_in, const int* in_sizes, int n_in,
                              void* d_out, int out_size) {
    const float* enc    = (const float*)d_in[0];
    const int*   trg    = (const int*)d_in[1];
    const float* embt   = (const float*)d_in[2];
    const float* attn_W = (const float*)d_in[3];
    const float* attn_b = (const float*)d_in[4];
    const float* attn_v = (const float*)d_in[5];
    const float* W_ih   = (const float*)d_in[6];
    const float* W_hh   = (const float*)d_in[7];
    const float* b_ih   = (const float*)d_in[8];
    const float* b_hh   = (const float*)d_in[9];
    const float* fc_W   = (const float*)d_in[10];
    const float* fc_b   = (const float*)d_in[11];
    float* outp = (float*)d_out;
    (void)in_sizes; (void)n_in;

    cudaFuncSetAttribute(k_fc, cudaFuncAttributeMaxDynamicSharedMemorySize, FC_SMEM);

    k_init<<<(B * VOC + 255) / 256, 256>>>(outp);
    k_wprep<<<dim3(NTILES / 8, NCH16), 256>>>(fc_W);
    k_encproj<<<(B * S) / 32, 128>>>(enc, attn_W, attn_b);

    for (int t = 0; t < NSTEP; t++) {
        if (t == 0) {
            k_score2<<<dim3(16, B), 128>>>(trg, embt, attn_W, attn_v, t);
        } else {
            cudaLaunchConfig_t cfg = {};
            cfg.gridDim = dim3(16, B, 1);
            cfg.blockDim = dim3(128, 1, 1);
            cfg.dynamicSmemBytes = 0;
            cfg.stream = 0;
            cudaLaunchAttribute at[1];
            at[0].id = cudaLaunchAttributeProgrammaticStreamSerialization;
            at[0].val.programmaticStreamSerializationAllowed = 1;
            cfg.attrs = at;
            cfg.numAttrs = 1;
            cudaLaunchKernelEx(&cfg, k_score2, trg, embt, attn_W, attn_v, t);
        }
        k_ctx<<<dim3(EHID / 128, B), 128>>>(enc);
        k_lstm<<<DHID, 256>>>(W_ih, W_hh, b_ih, b_hh, t);
        k_xprep<<<NCH16, 128>>>(t);
        k_fc<<<VOC / 256, 256, FC_SMEM>>>(fc_b, outp, t);
    }

    long long need = (long long)B * TT * VOC + (long long)B * TT;
    if ((long long)out_size >= need) {
        k_argmax<<<B * TT, 256>>>(outp, fc_W, fc_b,
                                  outp + (size_t)B * TT * VOC);
    }
}